// round 14
// baseline (speedup 1.0000x reference)
#include <cuda_runtime.h>
#include <cuda_bf16.h>
#include <mma.h>
#include <math.h>
#include <stdint.h>

using namespace nvcuda;

#define NN 50000
#define EE 800000
#define FIN 256
#define HD 64
#define CC 10
#define GG 64
#define NB_SCAN 196   // ceil(NN/256)

// ---------------- device scratch (no allocation allowed) ----------------
__device__ int   g_cnt[NN];
__device__ int   g_fill[NN];
__device__ int   g_rowstart[NN];
__device__ int   g_scan[NN];
__device__ int   g_blk[256];
__device__ int   g_blkoff[256];
__device__ float g_dis[NN];
__device__ int2  g_csr[EE];
__device__ __nv_bfloat16 g_bufHb[NN * HD]; // h as bf16 (128B per node row)
__device__ float g_bufA[NN * HD];          // activation fp32
__device__ int   g_gstart[GG + 1];
__device__ int   g_is64;

// ---------------- index accessor (int32 vs int64) ----------------
__device__ __forceinline__ long long get_idx(const void* p, long long i, int is64) {
    if (is64) return ((const long long*)p)[i];
    return (long long)((const int*)p)[i];
}

// ---------------- cp.async helpers (sm_80+ baseline PTX) ----------------
__device__ __forceinline__ void cp_async16(uint32_t dst, const void* src, int src_bytes) {
    asm volatile("cp.async.cg.shared.global [%0], [%1], 16, %2;"
                 :: "r"(dst), "l"(src), "r"(src_bytes));
}
__device__ __forceinline__ void cp_commit() {
    asm volatile("cp.async.commit_group;" ::: "memory");
}
template<int N> __device__ __forceinline__ void cp_wait() {
    asm volatile("cp.async.wait_group %0;" :: "n"(N) : "memory");
}

// ---------------- dtype detection + zero cnt/fill (fused) -----------------
__global__ void k_detect_zero(const int* __restrict__ words) {
    int i = blockIdx.x * blockDim.x + threadIdx.x;
    if (i < NN) { g_cnt[i] = 0; g_fill[i] = 0; }
    if (blockIdx.x == 0) {
        __shared__ int red[256];
        int tid = threadIdx.x;
        int acc = 0;
        for (int j = 0; j < 32; j++) {
            long long w = 1 + 2LL * (tid + 256LL * j * 97);
            if (w < 2LL * EE) acc |= words[w];
        }
        red[tid] = acc;
        __syncthreads();
        for (int s = 128; s > 0; s >>= 1) {
            if (tid < s) red[tid] |= red[tid + s];
            __syncthreads();
        }
        if (tid == 0) g_is64 = (red[0] == 0) ? 1 : 0;
    }
}

// ---------------- CSR build ----------------
__global__ void k_hist(const void* __restrict__ ei) {
    int e = blockIdx.x * blockDim.x + threadIdx.x;
    if (e >= EE) return;
    int d = (int)get_idx(ei, (long long)EE + e, g_is64);
    atomicAdd(&g_cnt[d], 1);
}

__global__ void k_scanA() {
    __shared__ int sh[256];
    int t = threadIdx.x;
    int i = blockIdx.x * 256 + t;
    int v = (i < NN) ? g_cnt[i] : 0;
    sh[t] = v;
    __syncthreads();
    #pragma unroll
    for (int off = 1; off < 256; off <<= 1) {
        int add = (t >= off) ? sh[t - off] : 0;
        __syncthreads();
        sh[t] += add;
        __syncthreads();
    }
    if (i < NN) g_scan[i] = sh[t];
    if (t == 255) g_blk[blockIdx.x] = sh[255];
}

__global__ void k_scanB() {
    __shared__ int sh[256];
    int t = threadIdx.x;
    int v = (t < NB_SCAN) ? g_blk[t] : 0;
    sh[t] = v;
    __syncthreads();
    #pragma unroll
    for (int off = 1; off < 256; off <<= 1) {
        int add = (t >= off) ? sh[t - off] : 0;
        __syncthreads();
        sh[t] += add;
        __syncthreads();
    }
    g_blkoff[t] = sh[t] - v;
}

__global__ void k_scanC_dis() {
    int i = blockIdx.x * 256 + threadIdx.x;
    if (i < NN) {
        int c = g_cnt[i];
        g_rowstart[i] = g_scan[i] - c + g_blkoff[blockIdx.x];
        g_dis[i] = rsqrtf((float)c + 1.0f);
    }
}

__global__ void k_fill(const void* __restrict__ ei) {
    int e = blockIdx.x * blockDim.x + threadIdx.x;
    if (e >= EE) return;
    int is64 = g_is64;
    int s = (int)get_idx(ei, e, is64);
    int d = (int)get_idx(ei, (long long)EE + e, is64);
    int pos = g_rowstart[d] + atomicAdd(&g_fill[d], 1);
    float w = g_dis[s] * g_dis[d];
    g_csr[pos] = make_int2(s, __float_as_int(w));
}

// ---------------- wmma TF32 GEMM, double-buffered cp.async pipeline -------
// Hout[M x 64](bf16) = A[M x K](fp32) @ W[K x 64](fp32)
// 256 threads = 8 warps; block tile 128x64; warp tile 32x32 (2x2 m16n16k8).
// K-tile = 32. Dynamic smem: As[2] 128x36, Ws[2] 32x68 (54272 B).
template<int K>
__global__ void __launch_bounds__(256) k_gemm(const float* __restrict__ A,
                                              const float* __restrict__ W,
                                              __nv_bfloat16* __restrict__ Out, int M) {
    extern __shared__ float smem[];
    const int ASZ = 128 * 36;   // floats per A buffer
    const int WSZ = 32 * 68;    // floats per W buffer
    float* AsBuf = smem;                 // 2 * ASZ
    float* WsBuf = smem + 2 * ASZ;       // 2 * WSZ
    int tid  = threadIdx.x;
    int wid  = tid >> 5;
    int lane = tid & 31;
    int r0   = blockIdx.x * 128;
    int wm   = (wid >> 1) * 32;
    int wn   = (wid & 1) * 32;

    // async-load one K-tile (A 128x32, W 32x64) into buffer `buf`
    auto loadTile = [&](int kt, int buf) {
        uint32_t abase = (uint32_t)__cvta_generic_to_shared(AsBuf + buf * ASZ);
        #pragma unroll
        for (int j = 0; j < 4; j++) {
            int s   = tid + j * 256;
            int row = s >> 3;
            int kq  = s & 7;
            int gr  = r0 + row;
            int grc = gr < M ? gr : (M - 1);          // clamp: address stays valid
            const float* src = &A[(size_t)grc * K + kt + kq * 4];
            int nbytes = (gr < M) ? 16 : 0;           // 0 => zero-fill
            cp_async16(abase + (uint32_t)(row * 36 + kq * 4) * 4u, src, nbytes);
        }
        uint32_t wbase = (uint32_t)__cvta_generic_to_shared(WsBuf + buf * WSZ);
        #pragma unroll
        for (int j = 0; j < 2; j++) {
            int s   = tid + j * 256;
            int row = s >> 4;
            int cq  = s & 15;
            cp_async16(wbase + (uint32_t)(row * 68 + cq * 4) * 4u,
                       &W[(size_t)(kt + row) * 64 + cq * 4], 16);
        }
        cp_commit();
    };

    wmma::fragment<wmma::accumulator, 16, 16, 8, float> acc[2][2];
    #pragma unroll
    for (int i = 0; i < 2; i++)
        #pragma unroll
        for (int j = 0; j < 2; j++)
            wmma::fill_fragment(acc[i][j], 0.0f);

    constexpr int NT = K / 32;
    loadTile(0, 0);

    #pragma unroll
    for (int t = 0; t < NT; t++) {
        if (t + 1 < NT) {
            loadTile((t + 1) * 32, (t + 1) & 1);
            cp_wait<1>();          // tile t has landed; t+1 still in flight
        } else {
            cp_wait<0>();
        }
        __syncthreads();
        float* As = AsBuf + (t & 1) * ASZ;
        float* Ws = WsBuf + (t & 1) * WSZ;
        #pragma unroll
        for (int kk = 0; kk < 32; kk += 8) {
            wmma::fragment<wmma::matrix_a, 16, 16, 8, wmma::precision::tf32, wmma::row_major> fa[2];
            wmma::fragment<wmma::matrix_b, 16, 16, 8, wmma::precision::tf32, wmma::row_major> fb[2];
            #pragma unroll
            for (int i = 0; i < 2; i++) {
                wmma::load_matrix_sync(fa[i], &As[(wm + i * 16) * 36 + kk], 36);
                #pragma unroll
                for (int e = 0; e < fa[i].num_elements; e++)
                    fa[i].x[e] = wmma::__float_to_tf32(fa[i].x[e]);
            }
            #pragma unroll
            for (int j = 0; j < 2; j++) {
                wmma::load_matrix_sync(fb[j], &Ws[kk * 68 + wn + j * 16], 68);
                #pragma unroll
                for (int e = 0; e < fb[j].num_elements; e++)
                    fb[j].x[e] = wmma::__float_to_tf32(fb[j].x[e]);
            }
            #pragma unroll
            for (int i = 0; i < 2; i++)
                #pragma unroll
                for (int j = 0; j < 2; j++)
                    wmma::mma_sync(acc[i][j], fa[i], fb[j], acc[i][j]);
        }
        __syncthreads();   // all warps done with buf (t&1) before it's refilled
    }

    // epilogue: frags -> per-warp 32x36 fp32 smem patch -> bf16 gmem rows
    float* stw = smem + wid * 1152;   // 32 x 36 floats = 4608 B/warp
    #pragma unroll
    for (int i = 0; i < 2; i++)
        #pragma unroll
        for (int j = 0; j < 2; j++)
            wmma::store_matrix_sync(&stw[(i * 16) * 36 + j * 16], acc[i][j], 36,
                                    wmma::mem_row_major);
    __syncwarp();
    int gr = r0 + wm + lane;
    if (gr < M) {
        const float* rowp = &stw[lane * 36];
        uint32_t pk[16];
        #pragma unroll
        for (int c = 0; c < 16; c++) {
            __nv_bfloat162 p = __float22bfloat162_rn(make_float2(rowp[2 * c], rowp[2 * c + 1]));
            pk[c] = *(uint32_t*)&p;
        }
        uint4* dst = (uint4*)&Out[(size_t)gr * 64 + wn];
        dst[0] = make_uint4(pk[0], pk[1], pk[2], pk[3]);
        dst[1] = make_uint4(pk[4], pk[5], pk[6], pk[7]);
        dst[2] = make_uint4(pk[8], pk[9], pk[10], pk[11]);
        dst[3] = make_uint4(pk[12], pk[13], pk[14], pk[15]);
    }
}

// ---------------- CSR gather (warp/node, bf16 features, fp32 accumulate) ----
__global__ void k_gather(const float* __restrict__ bias) {
    int warp = (blockIdx.x * blockDim.x + threadIdx.x) >> 5;
    int lane = threadIdx.x & 31;
    if (warp >= NN) return;
    int n   = warp;
    int beg = g_rowstart[n];
    int cnt = g_cnt[n];
    int end = beg + cnt;
    const __nv_bfloat162* __restrict__ H = (const __nv_bfloat162*)g_bufHb;

    float ax = 0.0f, ay = 0.0f;
    int e = beg;
    int end4 = beg + (cnt & ~3);
    for (; e < end4; e += 4) {
        int2 p0 = g_csr[e + 0];
        int2 p1 = g_csr[e + 1];
        int2 p2 = g_csr[e + 2];
        int2 p3 = g_csr[e + 3];
        float2 v0 = __bfloat1622float2(H[(size_t)p0.x * 32 + lane]);
        float2 v1 = __bfloat1622float2(H[(size_t)p1.x * 32 + lane]);
        float2 v2 = __bfloat1622float2(H[(size_t)p2.x * 32 + lane]);
        float2 v3 = __bfloat1622float2(H[(size_t)p3.x * 32 + lane]);
        float w0 = __int_as_float(p0.y);
        float w1 = __int_as_float(p1.y);
        float w2 = __int_as_float(p2.y);
        float w3 = __int_as_float(p3.y);
        ax += v0.x * w0 + v1.x * w1 + v2.x * w2 + v3.x * w3;
        ay += v0.y * w0 + v1.y * w1 + v2.y * w2 + v3.y * w3;
    }
    for (; e < end; e++) {
        int2 p0 = g_csr[e];
        float2 v0 = __bfloat1622float2(H[(size_t)p0.x * 32 + lane]);
        float w0 = __int_as_float(p0.y);
        ax += v0.x * w0;
        ay += v0.y * w0;
    }
    float dn = g_dis[n];
    float sn = dn * dn;
    float2 hv = __bfloat1622float2(H[(size_t)n * 32 + lane]);
    ax += hv.x * sn;
    ay += hv.y * sn;
    ax = fmaxf(ax + bias[2 * lane], 0.0f);
    ay = fmaxf(ay + bias[2 * lane + 1], 0.0f);
    ((float2*)g_bufA)[(size_t)n * 32 + lane] = make_float2(ax, ay);
}

// ---------------- pooling via sorted-batch segments ----------------
__global__ void k_bounds(const void* __restrict__ batch) {
    int g = threadIdx.x;
    if (g > GG) return;
    int is64 = g_is64;
    int lo = 0, hi = NN;
    while (lo < hi) {
        int mid = (lo + hi) >> 1;
        long long v = get_idx(batch, mid, is64);
        if (v < (long long)g) lo = mid + 1; else hi = mid;
    }
    g_gstart[g] = lo;
}

__global__ void k_poolfinal(const float* __restrict__ linW,
                            const float* __restrict__ linb,
                            float* __restrict__ out) {
    __shared__ float sp[4][64];
    int t = threadIdx.x;
    int f = t & 63;
    int r = t >> 6;
    int g = blockIdx.x;
    int s = g_gstart[g], eN = g_gstart[g + 1];
    float acc = 0.0f;
    for (int n = s + r; n < eN; n += 4)
        acc += g_bufA[(size_t)n * 64 + f];
    sp[r][f] = acc;
    __syncthreads();
    if (t < 64) {
        float total = sp[0][t] + sp[1][t] + sp[2][t] + sp[3][t];
        float cntf = (float)(eN - s);
        sp[0][t] = total / fmaxf(cntf, 1.0f);
    }
    __syncthreads();
    if (t < CC) {
        float o = linb[t];
        #pragma unroll 16
        for (int h = 0; h < HD; h++)
            o += sp[0][h] * linW[h * CC + t];
        out[g * CC + t] = o;
    }
}

// ---------------- host launcher (graph-capturable, serial) ----------------
extern "C" void kernel_launch(void* const* d_in, const int* in_sizes, int n_in,
                              void* d_out, int out_size) {
    const float* x    = (const float*)d_in[0];
    const void*  ei   = d_in[1];
    const void*  bat  = d_in[2];
    const float* W1   = (const float*)d_in[3];
    const float* b1   = (const float*)d_in[4];
    const float* W2   = (const float*)d_in[5];
    const float* b2   = (const float*)d_in[6];
    const float* W3   = (const float*)d_in[7];
    const float* b3   = (const float*)d_in[8];
    const float* linW = (const float*)d_in[9];
    const float* linb = (const float*)d_in[10];
    float* out = (float*)d_out;

    const int T = 256;
    int nbN    = (NN + T - 1) / T;           // 196
    int nbE    = (EE + T - 1) / T;           // 3125
    int nbGemm = (NN + 127) / 128;           // 391
    int nbGath = (NN * 32 + T - 1) / T;

    const int GSMEM = (2 * 128 * 36 + 2 * 32 * 68) * 4;   // 54272 B

    static __nv_bfloat16* pH = nullptr;
    static float* pA = nullptr;
    if (!pH) {
        void* tmp;
        cudaGetSymbolAddress(&tmp, g_bufHb); pH = (__nv_bfloat16*)tmp;
        cudaGetSymbolAddress(&tmp, g_bufA);  pA = (float*)tmp;
        cudaFuncSetAttribute(k_gemm<FIN>, cudaFuncAttributeMaxDynamicSharedMemorySize, GSMEM);
        cudaFuncSetAttribute(k_gemm<HD>,  cudaFuncAttributeMaxDynamicSharedMemorySize, GSMEM);
    }

    // preprocessing (serial); pipelined tf32 GEMM1 in profiled slot (index 3)
    k_detect_zero<<<nbN, T>>>((const int*)ei);           // 0
    k_hist<<<nbE, T>>>(ei);                              // 1
    k_scanA<<<NB_SCAN, 256>>>();                         // 2
    k_gemm<FIN><<<nbGemm, T, GSMEM>>>(x, W1, pH, NN);    // 3  <- ncu profiles this
    k_scanB<<<1, 256>>>();                               // 4
    k_scanC_dis<<<NB_SCAN, 256>>>();
    k_fill<<<nbE, T>>>(ei);
    k_bounds<<<1, GG + 1>>>(bat);

    // ---- layer 1 (gemm already issued above) ----
    k_gather<<<nbGath, T>>>(b1);

    // ---- layer 2 ----
    k_gemm<HD><<<nbGemm, T, GSMEM>>>(pA, W2, pH, NN);
    k_gather<<<nbGath, T>>>(b2);

    // ---- layer 3 ----
    k_gemm<HD><<<nbGemm, T, GSMEM>>>(pA, W3, pH, NN);
    k_gather<<<nbGath, T>>>(b3);

    // ---- pool + classify ----
    k_poolfinal<<<GG, 256>>>(linW, linb, out);
}

// round 15
// speedup vs baseline: 1.0667x; 1.0667x over previous
#include <cuda_runtime.h>
#include <cuda_bf16.h>
#include <mma.h>
#include <math.h>
#include <stdint.h>

using namespace nvcuda;

#define NN 50000
#define EE 800000
#define FIN 256
#define HD 64
#define CC 10
#define GG 64
#define NB_SCAN 196   // ceil(NN/256)

// ---------------- device scratch (no allocation allowed) ----------------
__device__ int   g_cnt[NN];
__device__ int   g_fill[NN];
__device__ int   g_rowstart[NN];
__device__ int   g_scan[NN];
__device__ int   g_blk[256];
__device__ int   g_blkoff[256];
__device__ float g_dis[NN];
__device__ int2  g_csr[EE];
__device__ __nv_bfloat16 g_bufHb[NN * HD]; // h as bf16 (128B per node row)
__device__ float g_bufA[NN * HD];          // activation fp32
__device__ int   g_gstart[GG + 1];
__device__ int   g_is64;

// ---------------- index accessor (int32 vs int64) ----------------
__device__ __forceinline__ long long get_idx(const void* p, long long i, int is64) {
    if (is64) return ((const long long*)p)[i];
    return (long long)((const int*)p)[i];
}

// ---------------- cp.async helpers (sm_80+ baseline PTX) ----------------
__device__ __forceinline__ void cp_async16(uint32_t dst, const void* src, int src_bytes) {
    asm volatile("cp.async.cg.shared.global [%0], [%1], 16, %2;"
                 :: "r"(dst), "l"(src), "r"(src_bytes));
}
__device__ __forceinline__ void cp_commit() {
    asm volatile("cp.async.commit_group;" ::: "memory");
}
template<int N> __device__ __forceinline__ void cp_wait() {
    asm volatile("cp.async.wait_group %0;" :: "n"(N) : "memory");
}

// ---------------- dtype detection + zero cnt/fill (fused) -----------------
__global__ void k_detect_zero(const int* __restrict__ words) {
    int i = blockIdx.x * blockDim.x + threadIdx.x;
    if (i < NN) { g_cnt[i] = 0; g_fill[i] = 0; }
    if (blockIdx.x == 0) {
        __shared__ int red[256];
        int tid = threadIdx.x;
        int acc = 0;
        for (int j = 0; j < 32; j++) {
            long long w = 1 + 2LL * (tid + 256LL * j * 97);
            if (w < 2LL * EE) acc |= words[w];
        }
        red[tid] = acc;
        __syncthreads();
        for (int s = 128; s > 0; s >>= 1) {
            if (tid < s) red[tid] |= red[tid + s];
            __syncthreads();
        }
        if (tid == 0) g_is64 = (red[0] == 0) ? 1 : 0;
    }
}

// ---------------- CSR build ----------------
__global__ void k_hist(const void* __restrict__ ei) {
    int e = blockIdx.x * blockDim.x + threadIdx.x;
    if (e >= EE) return;
    int d = (int)get_idx(ei, (long long)EE + e, g_is64);
    atomicAdd(&g_cnt[d], 1);
}

__global__ void k_scanA() {
    __shared__ int sh[256];
    int t = threadIdx.x;
    int i = blockIdx.x * 256 + t;
    int v = (i < NN) ? g_cnt[i] : 0;
    sh[t] = v;
    __syncthreads();
    #pragma unroll
    for (int off = 1; off < 256; off <<= 1) {
        int add = (t >= off) ? sh[t - off] : 0;
        __syncthreads();
        sh[t] += add;
        __syncthreads();
    }
    if (i < NN) g_scan[i] = sh[t];
    if (t == 255) g_blk[blockIdx.x] = sh[255];
}

__global__ void k_scanB() {
    __shared__ int sh[256];
    int t = threadIdx.x;
    int v = (t < NB_SCAN) ? g_blk[t] : 0;
    sh[t] = v;
    __syncthreads();
    #pragma unroll
    for (int off = 1; off < 256; off <<= 1) {
        int add = (t >= off) ? sh[t - off] : 0;
        __syncthreads();
        sh[t] += add;
        __syncthreads();
    }
    g_blkoff[t] = sh[t] - v;
}

__global__ void k_scanC_dis() {
    int i = blockIdx.x * 256 + threadIdx.x;
    if (i < NN) {
        int c = g_cnt[i];
        g_rowstart[i] = g_scan[i] - c + g_blkoff[blockIdx.x];
        g_dis[i] = rsqrtf((float)c + 1.0f);
    }
}

__global__ void k_fill(const void* __restrict__ ei) {
    int e = blockIdx.x * blockDim.x + threadIdx.x;
    if (e >= EE) return;
    int is64 = g_is64;
    int s = (int)get_idx(ei, e, is64);
    int d = (int)get_idx(ei, (long long)EE + e, is64);
    int pos = g_rowstart[d] + atomicAdd(&g_fill[d], 1);
    float w = g_dis[s] * g_dis[d];
    g_csr[pos] = make_int2(s, __float_as_int(w));
}

// ---------------- wmma TF32 GEMM, double-buffered cp.async (reg-disciplined)
// Hout[M x 64](bf16) = A[M x K](fp32) @ W[K x 64](fp32)
// 256 threads = 8 warps; block tile 128x64; warp tile 32x32 (2x2 m16n16k8).
// K-tile = 32. Dynamic smem: As[2] 128x36, Ws[2] 32x68 (54272 B).
// Main loop is NOT unrolled (reg pressure); per-thread offsets hoisted.
template<int K>
__global__ void __launch_bounds__(256, 2) k_gemm(const float* __restrict__ A,
                                                 const float* __restrict__ W,
                                                 __nv_bfloat16* __restrict__ Out, int M) {
    extern __shared__ float smem[];
    const int ASZ = 128 * 36;
    const int WSZ = 32 * 68;
    int tid  = threadIdx.x;
    int wid  = tid >> 5;
    int lane = tid & 31;
    int r0   = blockIdx.x * 128;
    int wm   = (wid >> 1) * 32;
    int wn   = (wid & 1) * 32;

    // hoisted per-thread load geometry
    // A: 1024 chunks of 16B; thread does rows tid>>3 (+32 per j), kq = tid&7
    int arow = tid >> 3;
    int akq  = tid & 7;
    // W: 512 chunks; rows tid>>4 (+16 per j), cq = tid&15
    int wrow = tid >> 4;
    int wcq  = tid & 15;

    uint32_t sA = (uint32_t)__cvta_generic_to_shared(smem);
    uint32_t sW = (uint32_t)__cvta_generic_to_shared(smem + 2 * ASZ);
    // per-thread smem byte offsets (within one buffer)
    uint32_t offA0 = (uint32_t)(arow * 36 + akq * 4) * 4u;
    uint32_t offW0 = (uint32_t)(wrow * 68 + wcq * 4) * 4u;
    // per-thread gmem row validity (A rows handled by this thread: arow + 32*j)
    const float* gA[4];
    int okA[4];
    #pragma unroll
    for (int j = 0; j < 4; j++) {
        int gr  = r0 + arow + 32 * j;
        okA[j]  = (gr < M) ? 16 : 0;
        int grc = (gr < M) ? gr : (M - 1);
        gA[j]   = &A[(size_t)grc * K + akq * 4];
    }
    const float* gW0 = &W[(size_t)wrow * 64 + wcq * 4];
    const float* gW1 = &W[(size_t)(wrow + 16) * 64 + wcq * 4];

    wmma::fragment<wmma::accumulator, 16, 16, 8, float> acc[2][2];
    #pragma unroll
    for (int i = 0; i < 2; i++)
        #pragma unroll
        for (int j = 0; j < 2; j++)
            wmma::fill_fragment(acc[i][j], 0.0f);

    // prologue: load tile 0 into buffer 0
    #pragma unroll
    for (int j = 0; j < 4; j++)
        cp_async16(sA + (uint32_t)(j * 32 * 36 * 4) + offA0, gA[j], okA[j]);
    cp_async16(sW + offW0, gW0, 16);
    cp_async16(sW + (uint32_t)(16 * 68 * 4) + offW0, gW1, 16);
    cp_commit();

    constexpr int NT = K / 32;
    #pragma unroll 1
    for (int t = 0; t < NT; t++) {
        int buf = t & 1;
        if (t + 1 < NT) {
            int nbuf = 1 - buf;
            int koff = (t + 1) * 32;   // element offset in K
            uint32_t aBufOff = (uint32_t)(nbuf * ASZ * 4);
            uint32_t wBufOff = (uint32_t)(nbuf * WSZ * 4);
            #pragma unroll
            for (int j = 0; j < 4; j++)
                cp_async16(sA + aBufOff + (uint32_t)(j * 32 * 36 * 4) + offA0,
                           gA[j] + koff, okA[j]);
            cp_async16(sW + wBufOff + offW0, gW0 + (size_t)koff * 64, 16);
            cp_async16(sW + wBufOff + (uint32_t)(16 * 68 * 4) + offW0,
                       gW1 + (size_t)koff * 64, 16);
            cp_commit();
            cp_wait<1>();
        } else {
            cp_wait<0>();
        }
        __syncthreads();
        float* As = smem + buf * ASZ;
        float* Ws = smem + 2 * ASZ + buf * WSZ;
        #pragma unroll
        for (int kk = 0; kk < 32; kk += 8) {
            wmma::fragment<wmma::matrix_a, 16, 16, 8, wmma::precision::tf32, wmma::row_major> fa[2];
            wmma::fragment<wmma::matrix_b, 16, 16, 8, wmma::precision::tf32, wmma::row_major> fb[2];
            #pragma unroll
            for (int i = 0; i < 2; i++) {
                wmma::load_matrix_sync(fa[i], &As[(wm + i * 16) * 36 + kk], 36);
                #pragma unroll
                for (int e = 0; e < fa[i].num_elements; e++)
                    fa[i].x[e] = wmma::__float_to_tf32(fa[i].x[e]);
            }
            #pragma unroll
            for (int j = 0; j < 2; j++) {
                wmma::load_matrix_sync(fb[j], &Ws[kk * 68 + wn + j * 16], 68);
                #pragma unroll
                for (int e = 0; e < fb[j].num_elements; e++)
                    fb[j].x[e] = wmma::__float_to_tf32(fb[j].x[e]);
            }
            #pragma unroll
            for (int i = 0; i < 2; i++)
                #pragma unroll
                for (int j = 0; j < 2; j++)
                    wmma::mma_sync(acc[i][j], fa[i], fb[j], acc[i][j]);
        }
        __syncthreads();
    }

    // epilogue: frags -> per-warp 32x36 fp32 smem patch -> bf16 gmem rows
    float* stw = smem + wid * 1152;
    #pragma unroll
    for (int i = 0; i < 2; i++)
        #pragma unroll
        for (int j = 0; j < 2; j++)
            wmma::store_matrix_sync(&stw[(i * 16) * 36 + j * 16], acc[i][j], 36,
                                    wmma::mem_row_major);
    __syncwarp();
    int gr = r0 + wm + lane;
    if (gr < M) {
        const float* rowp = &stw[lane * 36];
        uint32_t pk[16];
        #pragma unroll
        for (int c = 0; c < 16; c++) {
            __nv_bfloat162 p = __float22bfloat162_rn(make_float2(rowp[2 * c], rowp[2 * c + 1]));
            pk[c] = *(uint32_t*)&p;
        }
        uint4* dst = (uint4*)&Out[(size_t)gr * 64 + wn];
        dst[0] = make_uint4(pk[0], pk[1], pk[2], pk[3]);
        dst[1] = make_uint4(pk[4], pk[5], pk[6], pk[7]);
        dst[2] = make_uint4(pk[8], pk[9], pk[10], pk[11]);
        dst[3] = make_uint4(pk[12], pk[13], pk[14], pk[15]);
    }
}

// ---------------- CSR gather (warp/node, bf16 features, fp32 accumulate) ----
__global__ void k_gather(const float* __restrict__ bias) {
    int warp = (blockIdx.x * blockDim.x + threadIdx.x) >> 5;
    int lane = threadIdx.x & 31;
    if (warp >= NN) return;
    int n   = warp;
    int beg = g_rowstart[n];
    int cnt = g_cnt[n];
    int end = beg + cnt;
    const __nv_bfloat162* __restrict__ H = (const __nv_bfloat162*)g_bufHb;

    float ax = 0.0f, ay = 0.0f;
    int e = beg;
    int end4 = beg + (cnt & ~3);
    for (; e < end4; e += 4) {
        int2 p0 = g_csr[e + 0];
        int2 p1 = g_csr[e + 1];
        int2 p2 = g_csr[e + 2];
        int2 p3 = g_csr[e + 3];
        float2 v0 = __bfloat1622float2(H[(size_t)p0.x * 32 + lane]);
        float2 v1 = __bfloat1622float2(H[(size_t)p1.x * 32 + lane]);
        float2 v2 = __bfloat1622float2(H[(size_t)p2.x * 32 + lane]);
        float2 v3 = __bfloat1622float2(H[(size_t)p3.x * 32 + lane]);
        float w0 = __int_as_float(p0.y);
        float w1 = __int_as_float(p1.y);
        float w2 = __int_as_float(p2.y);
        float w3 = __int_as_float(p3.y);
        ax += v0.x * w0 + v1.x * w1 + v2.x * w2 + v3.x * w3;
        ay += v0.y * w0 + v1.y * w1 + v2.y * w2 + v3.y * w3;
    }
    for (; e < end; e++) {
        int2 p0 = g_csr[e];
        float2 v0 = __bfloat1622float2(H[(size_t)p0.x * 32 + lane]);
        float w0 = __int_as_float(p0.y);
        ax += v0.x * w0;
        ay += v0.y * w0;
    }
    float dn = g_dis[n];
    float sn = dn * dn;
    float2 hv = __bfloat1622float2(H[(size_t)n * 32 + lane]);
    ax += hv.x * sn;
    ay += hv.y * sn;
    ax = fmaxf(ax + bias[2 * lane], 0.0f);
    ay = fmaxf(ay + bias[2 * lane + 1], 0.0f);
    ((float2*)g_bufA)[(size_t)n * 32 + lane] = make_float2(ax, ay);
}

// ---------------- pooling via sorted-batch segments ----------------
__global__ void k_bounds(const void* __restrict__ batch) {
    int g = threadIdx.x;
    if (g > GG) return;
    int is64 = g_is64;
    int lo = 0, hi = NN;
    while (lo < hi) {
        int mid = (lo + hi) >> 1;
        long long v = get_idx(batch, mid, is64);
        if (v < (long long)g) lo = mid + 1; else hi = mid;
    }
    g_gstart[g] = lo;
}

__global__ void k_poolfinal(const float* __restrict__ linW,
                            const float* __restrict__ linb,
                            float* __restrict__ out) {
    __shared__ float sp[4][64];
    int t = threadIdx.x;
    int f = t & 63;
    int r = t >> 6;
    int g = blockIdx.x;
    int s = g_gstart[g], eN = g_gstart[g + 1];
    float acc = 0.0f;
    for (int n = s + r; n < eN; n += 4)
        acc += g_bufA[(size_t)n * 64 + f];
    sp[r][f] = acc;
    __syncthreads();
    if (t < 64) {
        float total = sp[0][t] + sp[1][t] + sp[2][t] + sp[3][t];
        float cntf = (float)(eN - s);
        sp[0][t] = total / fmaxf(cntf, 1.0f);
    }
    __syncthreads();
    if (t < CC) {
        float o = linb[t];
        #pragma unroll 16
        for (int h = 0; h < HD; h++)
            o += sp[0][h] * linW[h * CC + t];
        out[g * CC + t] = o;
    }
}

// ---------------- host launcher (graph-capturable, serial) ----------------
extern "C" void kernel_launch(void* const* d_in, const int* in_sizes, int n_in,
                              void* d_out, int out_size) {
    const float* x    = (const float*)d_in[0];
    const void*  ei   = d_in[1];
    const void*  bat  = d_in[2];
    const float* W1   = (const float*)d_in[3];
    const float* b1   = (const float*)d_in[4];
    const float* W2   = (const float*)d_in[5];
    const float* b2   = (const float*)d_in[6];
    const float* W3   = (const float*)d_in[7];
    const float* b3   = (const float*)d_in[8];
    const float* linW = (const float*)d_in[9];
    const float* linb = (const float*)d_in[10];
    float* out = (float*)d_out;

    const int T = 256;
    int nbN    = (NN + T - 1) / T;           // 196
    int nbE    = (EE + T - 1) / T;           // 3125
    int nbGemm = (NN + 127) / 128;           // 391
    int nbGath = (NN * 32 + T - 1) / T;

    const int GSMEM = (2 * 128 * 36 + 2 * 32 * 68) * 4;   // 54272 B

    static __nv_bfloat16* pH = nullptr;
    static float* pA = nullptr;
    if (!pH) {
        void* tmp;
        cudaGetSymbolAddress(&tmp, g_bufHb); pH = (__nv_bfloat16*)tmp;
        cudaGetSymbolAddress(&tmp, g_bufA);  pA = (float*)tmp;
        cudaFuncSetAttribute(k_gemm<FIN>, cudaFuncAttributeMaxDynamicSharedMemorySize, GSMEM);
        cudaFuncSetAttribute(k_gemm<HD>,  cudaFuncAttributeMaxDynamicSharedMemorySize, GSMEM);
    }

    // preprocessing (serial); pipelined tf32 GEMM1 in profiled slot (index 3)
    k_detect_zero<<<nbN, T>>>((const int*)ei);           // 0
    k_hist<<<nbE, T>>>(ei);                              // 1
    k_scanA<<<NB_SCAN, 256>>>();                         // 2
    k_gemm<FIN><<<nbGemm, T, GSMEM>>>(x, W1, pH, NN);    // 3  <- ncu profiles this
    k_scanB<<<1, 256>>>();                               // 4
    k_scanC_dis<<<NB_SCAN, 256>>>();
    k_fill<<<nbE, T>>>(ei);
    k_bounds<<<1, GG + 1>>>(bat);

    // ---- layer 1 (gemm already issued above) ----
    k_gather<<<nbGath, T>>>(b1);

    // ---- layer 2 ----
    k_gemm<HD><<<nbGemm, T, GSMEM>>>(pA, W2, pH, NN);
    k_gather<<<nbGath, T>>>(b2);

    // ---- layer 3 ----
    k_gemm<HD><<<nbGemm, T, GSMEM>>>(pA, W3, pH, NN);
    k_gather<<<nbGath, T>>>(b3);

    // ---- pool + classify ----
    k_poolfinal<<<GG, 256>>>(linW, linb, out);
}